// round 10
// baseline (speedup 1.0000x reference)
#include <cuda_runtime.h>
#include <math.h>
#include <float.h>
#include <limits.h>

#define LSIG 8192
#define NTH 512
#define NWARP 16
#define SRATE 30.0f

// exp(-2*pi*i*k/8192) for k = 0..4095
__device__ float2 g_tw[4096];

__global__ void tw_init_kernel() {
    int k = blockIdx.x * blockDim.x + threadIdx.x;
    if (k < 4096) {
        double a = -2.0 * 3.14159265358979323846 * (double)k / 8192.0;
        g_tw[k] = make_float2((float)cos(a), (float)sin(a));
    }
}

// ---------------- block reductions (512 threads, 16 warps) ----------------

__device__ __forceinline__ float bsumf(float v, float* s, int tid) {
    int lane = tid & 31, w = tid >> 5;
#pragma unroll
    for (int o = 16; o; o >>= 1) v += __shfl_down_sync(0xffffffffu, v, o);
    if (lane == 0) s[w] = v;
    __syncthreads();
    if (w == 0) {
        float x = (lane < NWARP) ? s[lane] : 0.0f;
#pragma unroll
        for (int o = 8; o; o >>= 1) x += __shfl_down_sync(0xffffffffu, x, o);
        if (lane == 0) s[0] = x;
    }
    __syncthreads();
    float r = s[0];
    __syncthreads();
    return r;
}

__device__ __forceinline__ float bmaxf(float v, float* s, int tid) {
    int lane = tid & 31, w = tid >> 5;
#pragma unroll
    for (int o = 16; o; o >>= 1) v = fmaxf(v, __shfl_down_sync(0xffffffffu, v, o));
    if (lane == 0) s[w] = v;
    __syncthreads();
    if (w == 0) {
        float x = (lane < NWARP) ? s[lane] : -FLT_MAX;
#pragma unroll
        for (int o = 8; o; o >>= 1) x = fmaxf(x, __shfl_down_sync(0xffffffffu, x, o));
        if (lane == 0) s[0] = x;
    }
    __syncthreads();
    float r = s[0];
    __syncthreads();
    return r;
}

__device__ __forceinline__ float bminf(float v, float* s, int tid) {
    int lane = tid & 31, w = tid >> 5;
#pragma unroll
    for (int o = 16; o; o >>= 1) v = fminf(v, __shfl_down_sync(0xffffffffu, v, o));
    if (lane == 0) s[w] = v;
    __syncthreads();
    if (w == 0) {
        float x = (lane < NWARP) ? s[lane] : FLT_MAX;
#pragma unroll
        for (int o = 8; o; o >>= 1) x = fminf(x, __shfl_down_sync(0xffffffffu, x, o));
        if (lane == 0) s[0] = x;
    }
    __syncthreads();
    float r = s[0];
    __syncthreads();
    return r;
}

__device__ __forceinline__ int bsumi(int v, int* s, int tid) {
    int lane = tid & 31, w = tid >> 5;
#pragma unroll
    for (int o = 16; o; o >>= 1) v += __shfl_down_sync(0xffffffffu, v, o);
    if (lane == 0) s[w] = v;
    __syncthreads();
    if (w == 0) {
        int x = (lane < NWARP) ? s[lane] : 0;
#pragma unroll
        for (int o = 8; o; o >>= 1) x += __shfl_down_sync(0xffffffffu, x, o);
        if (lane == 0) s[0] = x;
    }
    __syncthreads();
    int r = s[0];
    __syncthreads();
    return r;
}

__device__ __forceinline__ int bmini(int v, int* s, int tid) {
    int lane = tid & 31, w = tid >> 5;
#pragma unroll
    for (int o = 16; o; o >>= 1) v = min(v, __shfl_down_sync(0xffffffffu, v, o));
    if (lane == 0) s[w] = v;
    __syncthreads();
    if (w == 0) {
        int x = (lane < NWARP) ? s[lane] : INT_MAX;
#pragma unroll
        for (int o = 8; o; o >>= 1) x = min(x, __shfl_down_sync(0xffffffffu, x, o));
        if (lane == 0) s[0] = x;
    }
    __syncthreads();
    int r = s[0];
    __syncthreads();
    return r;
}

__device__ __forceinline__ int bmaxi(int v, int* s, int tid) {
    int lane = tid & 31, w = tid >> 5;
#pragma unroll
    for (int o = 16; o; o >>= 1) v = max(v, __shfl_down_sync(0xffffffffu, v, o));
    if (lane == 0) s[w] = v;
    __syncthreads();
    if (w == 0) {
        int x = (lane < NWARP) ? s[lane] : -2147483647;
#pragma unroll
        for (int o = 8; o; o >>= 1) x = max(x, __shfl_down_sync(0xffffffffu, x, o));
        if (lane == 0) s[0] = x;
    }
    __syncthreads();
    int r = s[0];
    __syncthreads();
    return r;
}

// two smallest indices across the block. a <= b on entry per thread.
__device__ __forceinline__ void bmin2i(int& a, int& b, int* s1, int* s2, int tid) {
    int lane = tid & 31, w = tid >> 5;
#pragma unroll
    for (int o = 16; o; o >>= 1) {
        int oa = __shfl_down_sync(0xffffffffu, a, o);
        int ob = __shfl_down_sync(0xffffffffu, b, o);
        int m1 = min(a, oa);
        int m2 = min(max(a, oa), min(b, ob));
        a = m1; b = m2;
    }
    if (lane == 0) { s1[w] = a; s2[w] = b; }
    __syncthreads();
    if (w == 0) {
        int x = (lane < NWARP) ? s1[lane] : INT_MAX;
        int y = (lane < NWARP) ? s2[lane] : INT_MAX;
#pragma unroll
        for (int o = 8; o; o >>= 1) {
            int oa = __shfl_down_sync(0xffffffffu, x, o);
            int ob = __shfl_down_sync(0xffffffffu, y, o);
            int m1 = min(x, oa);
            int m2 = min(max(x, oa), min(y, ob));
            x = m1; y = m2;
        }
        if (lane == 0) { s1[0] = x; s2[0] = y; }
    }
    __syncthreads();
    a = s1[0]; b = s2[0];
    __syncthreads();
}

// sqrt on the FMA pipe (avoid MUFU bottleneck): rsqrt bit-hack + 3 Newton steps.
// Safe at x == 0 (returns 0). Rel err ~1e-7 for normal x.
__device__ __forceinline__ float fast_sqrt(float x) {
    float xh = 0.5f * x;
    int i = __float_as_int(x);
    i = 0x5f375a86 - (i >> 1);
    float y = __int_as_float(i);
    y = y * (1.5f - xh * y * y);
    y = y * (1.5f - xh * y * y);
    y = y * (1.5f - xh * y * y);
    return x * y;
}

// dynamic smem: re[8192] | im[8192] | tw[4096] (float2)  = 98304 bytes
extern __shared__ float s_dyn[];

__global__ __launch_bounds__(NTH)
void feat_kernel(const float* __restrict__ x, float* __restrict__ out) {
    float* re = s_dyn;              // 8192 floats
    float* im = s_dyn + 8192;       // 8192 floats
    float2* tw = (float2*)(s_dyn + 16384);  // 4096 float2

    __shared__ float sf[NWARP];
    __shared__ int si[NWARP];
    __shared__ int si2[NWARP];

    const int tid = threadIdx.x;
    const int row = blockIdx.x;
    const float* __restrict__ sig = x + (size_t)row * LSIG;

    // ---- load signal, zero imag, stage twiddle table ----
#pragma unroll
    for (int k = 0; k < LSIG / NTH; k++) {
        int i = tid + k * NTH;
        re[i] = sig[i];
        im[i] = 0.0f;
    }
#pragma unroll
    for (int k = 0; k < 4096 / NTH; k++) {
        int i = tid + k * NTH;
        tw[i] = g_tw[i];
    }
    __syncthreads();

    // ---- phase 1: stats + peak/valley structure ----
    float mx = -FLT_MAX, mn = FLT_MAX, sum = 0.0f, ssq = 0.0f;
    int np = 0, nv = 0, p0 = INT_MAX, va = INT_MAX, vb = INT_MAX, vlast = -1;
#pragma unroll 4
    for (int i = tid; i < LSIG; i += NTH) {
        float v = re[i];
        mx = fmaxf(mx, v);
        mn = fminf(mn, v);
        sum += v;
        ssq = fmaf(v, v, ssq);
        if (i >= 1 && i <= LSIG - 2) {
            float a = re[i - 1], c = re[i + 1];
            if (v > a && v > c) { np++; p0 = min(p0, i); }
            if (v < a && v < c) {
                nv++;
                vlast = i;                 // i strictly increases per thread
                if (va == INT_MAX) va = i;
                else if (vb == INT_MAX) vb = i;
            }
        }
    }

    mx = bmaxf(mx, sf, tid);
    mn = bminf(mn, sf, tid);
    sum = bsumf(sum, sf, tid);
    ssq = bsumf(ssq, sf, tid);
    np = bsumi(np, si, tid);
    nv = bsumi(nv, si, tid);
    p0 = bmini(p0, si, tid);
    bmin2i(va, vb, si, si2, tid);
    vlast = bmaxi(vlast, si, tid);

    const bool valid = (np >= 1) && (nv >= 2);
    const int P0 = valid ? p0 : 0;
    const int V0 = valid ? va : 0;
    const int V1 = valid ? vb : 0;
    const int VL = valid ? vlast : 0;

    const float sp0 = re[P0], sv0 = re[V0];
    const float PH = sp0 - sv0;
    const float hh = (PH + sv0) * 0.5f;

    // ---- phase 2: trapezoid areas + half-height width ----
    float pa = 0.0f, a2 = 0.0f, a1 = 0.0f;
    int li = INT_MAX, ri = -1;
    const float hs = 0.5f / SRATE;
#pragma unroll 4
    for (int i = tid; i < LSIG; i += NTH) {
        float v = re[i];
        if (i < LSIG - 1) {
            float seg = (v + re[i + 1]) * hs;
            if (i >= V0 && i <= VL - 2) pa += seg;
            if (i >= P0 && i <= V1 - 2) a2 += seg;
            if (i >= V0 && i <= P0 - 2) a1 += seg;
        }
        if (v >= hh) {
            if (i >= V0 && i < P0) li = min(li, i);
            if (i > V0 && i <= P0) ri = max(ri, i);
        }
    }
    pa = bsumf(pa, sf, tid);
    a2 = bsumf(a2, sf, tid);
    a1 = bsumf(a1, sf, tid);
    li = bmini(li, si, tid);
    ri = bmaxi(ri, si, tid);
    if (li == INT_MAX) li = V0;
    if (ri == -1) ri = P0;
    const float pwhh = (float)(ri - li) * (1.0f / SRATE);

    __syncthreads();

    // ---- phase 3: in-place DIF FFT (order-scrambled output, magnitudes only) ----
    // stage 0: radix-2, half = 4096, twiddle exp(-2*pi*i*t/8192) = tw[t]
#pragma unroll
    for (int k = 0; k < 4096 / NTH; k++) {
        int t = tid + k * NTH;
        float ar = re[t], ai = im[t];
        float br = re[t + 4096], bi = im[t + 4096];
        re[t] = ar + br;
        im[t] = ai + bi;
        float dr = ar - br, di = ai - bi;
        float2 w = tw[t];
        re[t + 4096] = dr * w.x - di * w.y;
        im[t + 4096] = dr * w.y + di * w.x;
    }
    __syncthreads();

    // stages 1..6: radix-4 on each 4096 half, m = 1024,256,64,16,4,1
#pragma unroll
    for (int s = 0; s < 6; s++) {
        const int lm = 10 - 2 * s;
        const int m = 1 << lm;
        const int tsh = 11 - lm;  // twiddle stride = 2048/m
#pragma unroll
        for (int k = 0; k < 2048 / NTH; k++) {
            int t = tid + k * NTH;
            int j = t & (m - 1);
            int base = ((t - j) << 2) + j;  // (t/m)*4m + j

            float y0r = re[base],         y0i = im[base];
            float y1r = re[base + m],     y1i = im[base + m];
            float y2r = re[base + 2 * m], y2i = im[base + 2 * m];
            float y3r = re[base + 3 * m], y3i = im[base + 3 * m];

            float t0r = y0r + y2r, t0i = y0i + y2i;
            float t1r = y0r - y2r, t1i = y0i - y2i;
            float t2r = y1r + y3r, t2i = y1i + y3i;
            float t3r = y1r - y3r, t3i = y1i - y3i;

            // z0 = t0+t2; z1 = t1 - i*t3; z2 = t0-t2; z3 = t1 + i*t3
            float z1r = t1r + t3i, z1i = t1i - t3r;
            float z2r = t0r - t2r, z2i = t0i - t2i;
            float z3r = t1r - t3i, z3i = t1i + t3r;

            float2 w1 = tw[j << tsh];
            float w2r = w1.x * w1.x - w1.y * w1.y;
            float w2i = 2.0f * w1.x * w1.y;
            float w3r = w2r * w1.x - w2i * w1.y;
            float w3i = w2r * w1.y + w2i * w1.x;

            re[base] = t0r + t2r;
            im[base] = t0i + t2i;
            re[base + m] = z1r * w1.x - z1i * w1.y;
            im[base + m] = z1r * w1.y + z1i * w1.x;
            re[base + 2 * m] = z2r * w2r - z2i * w2i;
            im[base + 2 * m] = z2r * w2i + z2i * w2r;
            re[base + 3 * m] = z3r * w3r - z3i * w3i;
            im[base + 3 * m] = z3r * w3i + z3i * w3r;
        }
        __syncthreads();
    }

    // ---- magnitude sum (FMA-pipe sqrt) ----
    float ms = 0.0f;
#pragma unroll 4
    for (int i = tid; i < LSIG; i += NTH) {
        float rr = re[i], ii = im[i];
        ms += fast_sqrt(fmaf(rr, rr, ii * ii));
    }
    ms = bsumf(ms, sf, tid);
    const float fftm = ms * (1.0f / (float)LSIG);

    if (tid == 0) {
        float mean = sum * (1.0f / (float)LSIG);
        float var = (ssq - sum * mean) * (1.0f / (float)(LSIG - 1));
        float* o = out + (size_t)row * 10;
        o[0] = mx;
        o[1] = mx - mn;
        o[2] = var;
        o[3] = sqrtf(var);
        o[4] = fftm;
        o[5] = valid ? pa : 0.0f;
        o[6] = valid ? a2 : 0.0f;
        o[7] = valid ? PH : 0.0f;
        o[8] = valid ? a1 : 0.0f;
        o[9] = valid ? pwhh : 0.0f;
    }
}

extern "C" void kernel_launch(void* const* d_in, const int* in_sizes, int n_in,
                              void* d_out, int out_size) {
    const float* x = (const float*)d_in[0];
    float* out = (float*)d_out;
    int nrow = in_sizes[0] / LSIG;

    (void)n_in; (void)out_size;

    cudaFuncSetAttribute(feat_kernel, cudaFuncAttributeMaxDynamicSharedMemorySize, 98304);

    tw_init_kernel<<<16, 256>>>();
    feat_kernel<<<nrow, NTH, 98304>>>(x, out);
}

// round 11
// speedup vs baseline: 1.3794x; 1.3794x over previous
#include <cuda_runtime.h>
#include <math.h>
#include <float.h>
#include <limits.h>

#define LSIG 8192
#define N2   4096
#define NTH  512
#define NWARP 16
#define SRATE 30.0f

// quarter-wave table: (cos, sin)(2*pi*k/8192) for k = 0..1024
__device__ float2 g_tab[1025];

__global__ void tab_init_kernel() {
    int k = blockIdx.x * blockDim.x + threadIdx.x;
    if (k <= 1024) {
        double a = 2.0 * 3.14159265358979323846 * (double)k / 8192.0;
        g_tab[k] = make_float2((float)cos(a), (float)sin(a));
    }
}

// ---------------- block reductions (512 threads, 16 warps) ----------------

__device__ __forceinline__ float bsumf(float v, float* s, int tid) {
    int lane = tid & 31, w = tid >> 5;
#pragma unroll
    for (int o = 16; o; o >>= 1) v += __shfl_down_sync(0xffffffffu, v, o);
    if (lane == 0) s[w] = v;
    __syncthreads();
    if (w == 0) {
        float x = (lane < NWARP) ? s[lane] : 0.0f;
#pragma unroll
        for (int o = 8; o; o >>= 1) x += __shfl_down_sync(0xffffffffu, x, o);
        if (lane == 0) s[0] = x;
    }
    __syncthreads();
    float r = s[0];
    __syncthreads();
    return r;
}

__device__ __forceinline__ float bmaxf(float v, float* s, int tid) {
    int lane = tid & 31, w = tid >> 5;
#pragma unroll
    for (int o = 16; o; o >>= 1) v = fmaxf(v, __shfl_down_sync(0xffffffffu, v, o));
    if (lane == 0) s[w] = v;
    __syncthreads();
    if (w == 0) {
        float x = (lane < NWARP) ? s[lane] : -FLT_MAX;
#pragma unroll
        for (int o = 8; o; o >>= 1) x = fmaxf(x, __shfl_down_sync(0xffffffffu, x, o));
        if (lane == 0) s[0] = x;
    }
    __syncthreads();
    float r = s[0];
    __syncthreads();
    return r;
}

__device__ __forceinline__ float bminf(float v, float* s, int tid) {
    int lane = tid & 31, w = tid >> 5;
#pragma unroll
    for (int o = 16; o; o >>= 1) v = fminf(v, __shfl_down_sync(0xffffffffu, v, o));
    if (lane == 0) s[w] = v;
    __syncthreads();
    if (w == 0) {
        float x = (lane < NWARP) ? s[lane] : FLT_MAX;
#pragma unroll
        for (int o = 8; o; o >>= 1) x = fminf(x, __shfl_down_sync(0xffffffffu, x, o));
        if (lane == 0) s[0] = x;
    }
    __syncthreads();
    float r = s[0];
    __syncthreads();
    return r;
}

__device__ __forceinline__ int bsumi(int v, int* s, int tid) {
    int lane = tid & 31, w = tid >> 5;
#pragma unroll
    for (int o = 16; o; o >>= 1) v += __shfl_down_sync(0xffffffffu, v, o);
    if (lane == 0) s[w] = v;
    __syncthreads();
    if (w == 0) {
        int x = (lane < NWARP) ? s[lane] : 0;
#pragma unroll
        for (int o = 8; o; o >>= 1) x += __shfl_down_sync(0xffffffffu, x, o);
        if (lane == 0) s[0] = x;
    }
    __syncthreads();
    int r = s[0];
    __syncthreads();
    return r;
}

__device__ __forceinline__ int bmini(int v, int* s, int tid) {
    int lane = tid & 31, w = tid >> 5;
#pragma unroll
    for (int o = 16; o; o >>= 1) v = min(v, __shfl_down_sync(0xffffffffu, v, o));
    if (lane == 0) s[w] = v;
    __syncthreads();
    if (w == 0) {
        int x = (lane < NWARP) ? s[lane] : INT_MAX;
#pragma unroll
        for (int o = 8; o; o >>= 1) x = min(x, __shfl_down_sync(0xffffffffu, x, o));
        if (lane == 0) s[0] = x;
    }
    __syncthreads();
    int r = s[0];
    __syncthreads();
    return r;
}

__device__ __forceinline__ int bmaxi(int v, int* s, int tid) {
    int lane = tid & 31, w = tid >> 5;
#pragma unroll
    for (int o = 16; o; o >>= 1) v = max(v, __shfl_down_sync(0xffffffffu, v, o));
    if (lane == 0) s[w] = v;
    __syncthreads();
    if (w == 0) {
        int x = (lane < NWARP) ? s[lane] : -2147483647;
#pragma unroll
        for (int o = 8; o; o >>= 1) x = max(x, __shfl_down_sync(0xffffffffu, x, o));
        if (lane == 0) s[0] = x;
    }
    __syncthreads();
    int r = s[0];
    __syncthreads();
    return r;
}

// two smallest indices across the block. a <= b on entry per thread.
__device__ __forceinline__ void bmin2i(int& a, int& b, int* s1, int* s2, int tid) {
    int lane = tid & 31, w = tid >> 5;
#pragma unroll
    for (int o = 16; o; o >>= 1) {
        int oa = __shfl_down_sync(0xffffffffu, a, o);
        int ob = __shfl_down_sync(0xffffffffu, b, o);
        int m1 = min(a, oa);
        int m2 = min(max(a, oa), min(b, ob));
        a = m1; b = m2;
    }
    if (lane == 0) { s1[w] = a; s2[w] = b; }
    __syncthreads();
    if (w == 0) {
        int x = (lane < NWARP) ? s1[lane] : INT_MAX;
        int y = (lane < NWARP) ? s2[lane] : INT_MAX;
#pragma unroll
        for (int o = 8; o; o >>= 1) {
            int oa = __shfl_down_sync(0xffffffffu, x, o);
            int ob = __shfl_down_sync(0xffffffffu, y, o);
            int m1 = min(x, oa);
            int m2 = min(max(x, oa), min(y, ob));
            x = m1; y = m2;
        }
        if (lane == 0) { s1[0] = x; s2[0] = y; }
    }
    __syncthreads();
    a = s1[0]; b = s2[0];
    __syncthreads();
}

// sqrt on the FMA pipe (avoid MUFU bottleneck). Safe at x == 0.
__device__ __forceinline__ float fast_sqrt(float x) {
    float xh = 0.5f * x;
    int i = __float_as_int(x);
    i = 0x5f375a86 - (i >> 1);
    float y = __int_as_float(i);
    y = y * (1.5f - xh * y * y);
    y = y * (1.5f - xh * y * y);
    y = y * (1.5f - xh * y * y);
    return x * y;
}

// XOR bank swizzle on complex index; kills write conflicts in s<32 Stockham
// stages while keeping i / i+1024c reads conflict-free (1024c doesn't touch
// the swizzled bits).
__device__ __forceinline__ int swz(int a) { return a ^ ((a >> 4) & 15); }

// scalar signal load from swizzled complex buffer (float index i in [0,8192))
__device__ __forceinline__ float sload(const float2* buf, int i) {
    int a = i >> 1;
    int pa = a ^ ((a >> 4) & 15);
    return ((const float*)buf)[2 * pa + (i & 1)];
}

// e^{-2*pi*i*q/8192} for q in [0, 2048), via quarter-wave table
__device__ __forceinline__ float2 Wq(const float2* __restrict__ tab, int q) {
    if (q <= 1024) {
        float2 t = tab[q];
        return make_float2(t.x, -t.y);
    }
    float2 t = tab[2048 - q];
    return make_float2(t.y, -t.x);
}

__device__ __forceinline__ float2 cmul(float2 a, float2 b) {
    return make_float2(fmaf(a.x, b.x, -(a.y * b.y)), fmaf(a.x, b.y, a.y * b.x));
}

// dynamic smem: bufA[4096] | bufB[4096] | tab[1025]  (float2) = 73736 bytes
extern __shared__ float2 s_dyn2[];

__global__ __launch_bounds__(NTH, 3)
void feat_kernel(const float* __restrict__ x, float* __restrict__ out) {
    float2* bufA = s_dyn2;
    float2* bufB = s_dyn2 + N2;
    float2* tab = s_dyn2 + 2 * N2;

    __shared__ float sf[NWARP];
    __shared__ int si[NWARP];
    __shared__ int si2[NWARP];

    const int tid = threadIdx.x;
    const float2* __restrict__ sig2 =
        (const float2*)(x + (size_t)blockIdx.x * LSIG);

    // stage twiddle table
#pragma unroll
    for (int i = tid; i < 1025; i += NTH) tab[i] = g_tab[i];

    // ---- pass A: load (even/odd packed complex), stats, swizzled store ----
    float mx = -FLT_MAX, mn = FLT_MAX, sum = 0.0f, ssq = 0.0f;
#pragma unroll
    for (int k = 0; k < N2 / NTH; k++) {
        int n = tid + k * NTH;
        float2 v = sig2[n];
        mx = fmaxf(mx, fmaxf(v.x, v.y));
        mn = fminf(mn, fminf(v.x, v.y));
        sum += v.x + v.y;
        ssq = fmaf(v.x, v.x, ssq);
        ssq = fmaf(v.y, v.y, ssq);
        bufA[swz(n)] = v;
    }
    __syncthreads();

    // ---- phase 1: peak/valley structure ----
    int np = 0, nv = 0, p0 = INT_MAX, va = INT_MAX, vb = INT_MAX, vlast = -1;
#pragma unroll 4
    for (int i = tid; i < LSIG; i += NTH) {
        if (i >= 1 && i <= LSIG - 2) {
            float a = sload(bufA, i - 1);
            float v = sload(bufA, i);
            float c = sload(bufA, i + 1);
            if (v > a && v > c) { np++; p0 = min(p0, i); }
            if (v < a && v < c) {
                nv++;
                vlast = i;  // i strictly increases per thread
                if (va == INT_MAX) va = i;
                else if (vb == INT_MAX) vb = i;
            }
        }
    }

    mx = bmaxf(mx, sf, tid);
    mn = bminf(mn, sf, tid);
    sum = bsumf(sum, sf, tid);
    ssq = bsumf(ssq, sf, tid);
    np = bsumi(np, si, tid);
    nv = bsumi(nv, si, tid);
    p0 = bmini(p0, si, tid);
    bmin2i(va, vb, si, si2, tid);
    vlast = bmaxi(vlast, si, tid);

    const bool valid = (np >= 1) && (nv >= 2);
    const int P0 = valid ? p0 : 0;
    const int V0 = valid ? va : 0;
    const int V1 = valid ? vb : 0;
    const int VL = valid ? vlast : 0;

    const float sp0 = sload(bufA, P0), sv0 = sload(bufA, V0);
    const float PH = sp0 - sv0;
    const float hh = (PH + sv0) * 0.5f;

    // ---- phase 2: trapezoid areas + half-height width ----
    float pa = 0.0f, a2 = 0.0f, a1 = 0.0f;
    int li = INT_MAX, ri = -1;
    const float hs = 0.5f / SRATE;
#pragma unroll 4
    for (int i = tid; i < LSIG; i += NTH) {
        float v = sload(bufA, i);
        if (i < LSIG - 1) {
            float seg = (v + sload(bufA, i + 1)) * hs;
            if (i >= V0 && i <= VL - 2) pa += seg;
            if (i >= P0 && i <= V1 - 2) a2 += seg;
            if (i >= V0 && i <= P0 - 2) a1 += seg;
        }
        if (v >= hh) {
            if (i >= V0 && i < P0) li = min(li, i);
            if (i > V0 && i <= P0) ri = max(ri, i);
        }
    }
    pa = bsumf(pa, sf, tid);
    a2 = bsumf(a2, sf, tid);
    a1 = bsumf(a1, sf, tid);
    li = bmini(li, si, tid);
    ri = bmaxi(ri, si, tid);
    if (li == INT_MAX) li = V0;
    if (ri == -1) ri = P0;
    const float pwhh = (float)(ri - li) * (1.0f / SRATE);

    __syncthreads();

    // ---- 4096-point Stockham radix-4 FFT (natural-order output) ----
    // stage t: n = 4096 >> 2t, s = 4^t, m = n/4; butterfly i in [0,1024):
    //   p = i >> 2t, q = i & (s-1); reads cur[i + 1024*c];
    //   writes nxt[i + 3*(i & ~(s-1)) + r*s], twiddle w1 = W(p * 8192/n).
    float2* cur = bufA;
    float2* nxt = bufB;
#pragma unroll
    for (int t = 0; t < 6; t++) {
        const int s = 1 << (2 * t);
        const int sh = 1 + 2 * t;  // 8192/n = 2*4^t
#pragma unroll
        for (int k = 0; k < 2; k++) {
            int i = tid + k * NTH;
            int ps = i & ~(s - 1);  // p*s
            int p = i >> (2 * t);
            int ri2 = swz(i);
            float2 a = cur[ri2];
            float2 b = cur[ri2 + 1024];
            float2 c = cur[ri2 + 2048];
            float2 d = cur[ri2 + 3072];

            float2 w1 = Wq(tab, p << sh);
            float2 w2 = cmul(w1, w1);
            float2 w3 = cmul(w2, w1);

            float2 apc = make_float2(a.x + c.x, a.y + c.y);
            float2 amc = make_float2(a.x - c.x, a.y - c.y);
            float2 bpd = make_float2(b.x + d.x, b.y + d.y);
            float2 jbmd = make_float2(-(b.y - d.y), b.x - d.x);

            int wb = i + 3 * ps;
            nxt[swz(wb)] = make_float2(apc.x + bpd.x, apc.y + bpd.y);
            nxt[swz(wb + s)] =
                cmul(w1, make_float2(amc.x - jbmd.x, amc.y - jbmd.y));
            nxt[swz(wb + 2 * s)] =
                cmul(w2, make_float2(apc.x - bpd.x, apc.y - bpd.y));
            nxt[swz(wb + 3 * s)] =
                cmul(w3, make_float2(amc.x + jbmd.x, amc.y + jbmd.y));
        }
        __syncthreads();
        float2* tmp = cur; cur = nxt; nxt = tmp;
    }
    // 6 stages -> result back in bufA (== cur)

    // ---- real-FFT unpack + magnitude sum ----
    // Z = FFT(x_even + i*x_odd);  E = (Z[k]+conj Z[N2-k])/2, O = (Z[k]-conj Z[N2-k])/(2i)
    // X[k] = E + W^k O,  X[k+N2] = E - W^k O,  W = e^{-2pi i k/8192}
    float ms = 0.0f;
#pragma unroll
    for (int k0 = 0; k0 < N2 / NTH; k0++) {
        int k = tid + k0 * NTH;
        int kp = (N2 - k) & (N2 - 1);
        float2 Zk = cur[swz(k)];
        float2 Zp = cur[swz(kp)];
        float Er = 0.5f * (Zk.x + Zp.x);
        float Ei = 0.5f * (Zk.y - Zp.y);
        float Or = 0.5f * (Zk.y + Zp.y);
        float Oi = 0.5f * (Zp.x - Zk.x);
        float2 w;
        if (k < 2048) {
            w = Wq(tab, k);
        } else {
            float2 u = Wq(tab, k - 2048);
            w = make_float2(u.y, -u.x);  // -i * u
        }
        float2 wo = cmul(w, make_float2(Or, Oi));
        float xr = Er + wo.x, xi = Ei + wo.y;
        float yr = Er - wo.x, yi = Ei - wo.y;
        ms += fast_sqrt(fmaf(xr, xr, xi * xi));
        ms += fast_sqrt(fmaf(yr, yr, yi * yi));
    }
    ms = bsumf(ms, sf, tid);
    const float fftm = ms * (1.0f / (float)LSIG);

    if (tid == 0) {
        float mean = sum * (1.0f / (float)LSIG);
        float var = (ssq - sum * mean) * (1.0f / (float)(LSIG - 1));
        float* o = out + (size_t)blockIdx.x * 10;
        o[0] = mx;
        o[1] = mx - mn;
        o[2] = var;
        o[3] = sqrtf(var);
        o[4] = fftm;
        o[5] = valid ? pa : 0.0f;
        o[6] = valid ? a2 : 0.0f;
        o[7] = valid ? PH : 0.0f;
        o[8] = valid ? a1 : 0.0f;
        o[9] = valid ? pwhh : 0.0f;
    }
}

extern "C" void kernel_launch(void* const* d_in, const int* in_sizes, int n_in,
                              void* d_out, int out_size) {
    const float* x = (const float*)d_in[0];
    float* out = (float*)d_out;
    int nrow = in_sizes[0] / LSIG;

    (void)n_in; (void)out_size;

    const int smem = (2 * N2 + 1025) * (int)sizeof(float2);  // 73736
    cudaFuncSetAttribute(feat_kernel, cudaFuncAttributeMaxDynamicSharedMemorySize, smem);

    tab_init_kernel<<<5, 256>>>();
    feat_kernel<<<nrow, NTH, smem>>>(x, out);
}

// round 12
// speedup vs baseline: 1.8059x; 1.3092x over previous
#include <cuda_runtime.h>
#include <math.h>
#include <float.h>
#include <limits.h>

#define LSIG 8192
#define N2   4096
#define NTH  512
#define NWARP 16
#define SRATE 30.0f

// quarter-wave table: (cos, sin)(2*pi*k/8192) for k = 0..1024
__device__ float2 g_tab[1025];

__global__ void tab_init_kernel() {
    int k = blockIdx.x * blockDim.x + threadIdx.x;
    if (k <= 1024) {
        double a = 2.0 * 3.14159265358979323846 * (double)k / 8192.0;
        g_tab[k] = make_float2((float)cos(a), (float)sin(a));
    }
}

// sqrt on the FMA pipe (avoid MUFU bottleneck). Safe at x == 0.
// 2 Newton steps: rel err ~5e-6, well under the 1e-3 gate.
__device__ __forceinline__ float fast_sqrt(float x) {
    float xh = 0.5f * x;
    int i = __float_as_int(x);
    i = 0x5f375a86 - (i >> 1);
    float y = __int_as_float(i);
    y = y * (1.5f - xh * y * y);
    y = y * (1.5f - xh * y * y);
    return x * y;
}

// XOR bank swizzle on complex index (FFT stages only).
__device__ __forceinline__ int swz(int a) { return a ^ ((a >> 4) & 15); }

// e^{-2*pi*i*q/8192} for q in [0, 2048), via quarter-wave table
__device__ __forceinline__ float2 Wq(const float2* __restrict__ tab, int q) {
    if (q <= 1024) {
        float2 t = tab[q];
        return make_float2(t.x, -t.y);
    }
    float2 t = tab[2048 - q];
    return make_float2(t.y, -t.x);
}

__device__ __forceinline__ float2 cmul(float2 a, float2 b) {
    return make_float2(fmaf(a.x, b.x, -(a.y * b.y)), fmaf(a.x, b.y, a.y * b.x));
}

// dynamic smem: bufA[4096] | bufB[4096] | tab[1025]  (float2) = 73736 bytes
extern __shared__ float2 s_dyn2[];

__global__ __launch_bounds__(NTH, 3)
void feat_kernel(const float* __restrict__ x, float* __restrict__ out) {
    float2* bufA = s_dyn2;
    float2* bufB = s_dyn2 + N2;
    float2* tab = s_dyn2 + 2 * N2;

    __shared__ float fp1[4][NWARP];
    __shared__ int ip1[6][NWARP];
    __shared__ float fres[4];
    __shared__ int ires[6];

    const int tid = threadIdx.x;
    const int lane = tid & 31;
    const int wrp = tid >> 5;
    const float2* __restrict__ sig2 =
        (const float2*)(x + (size_t)blockIdx.x * LSIG);

    // stage twiddle table
#pragma unroll
    for (int i = tid; i < 1025; i += NTH) tab[i] = g_tab[i];

    // ---- pass A: load (natural layout == even/odd packed complex) + stats ----
    float mx = -FLT_MAX, mn = FLT_MAX, sum = 0.0f, ssq = 0.0f;
#pragma unroll
    for (int k = 0; k < N2 / NTH; k++) {
        int n = tid + k * NTH;
        float2 v = sig2[n];
        mx = fmaxf(mx, fmaxf(v.x, v.y));
        mn = fminf(mn, fminf(v.x, v.y));
        sum += v.x + v.y;
        ssq = fmaf(v.x, v.x, ssq);
        ssq = fmaf(v.y, v.y, ssq);
        bufA[n] = v;  // natural: ((float*)bufA)[i] == sig[i]
    }
    __syncthreads();

    const float* __restrict__ re = (const float*)bufA;

    // ---- phase 1: peak/valley structure (natural reads, immediate offsets) ----
    int np = 0, nv = 0, p0 = INT_MAX, va = INT_MAX, vb = INT_MAX, vlast = -1;
#pragma unroll 4
    for (int i = tid; i < LSIG; i += NTH) {
        float v = re[i];
        float a = re[max(i - 1, 0)];
        float c = re[min(i + 1, LSIG - 1)];
        bool inb = (i >= 1) && (i <= LSIG - 2);
        if (inb && v > a && v > c) { np++; p0 = min(p0, i); }
        if (inb && v < a && v < c) {
            nv++;
            vlast = i;  // i strictly increases per thread
            if (va == INT_MAX) va = i;
            else if (vb == INT_MAX) vb = i;
        }
    }

    // ---- batched block reduction: all phase-1 quantities, 2 barriers ----
#pragma unroll
    for (int o = 16; o; o >>= 1) {
        mx = fmaxf(mx, __shfl_down_sync(0xffffffffu, mx, o));
        mn = fminf(mn, __shfl_down_sync(0xffffffffu, mn, o));
        sum += __shfl_down_sync(0xffffffffu, sum, o);
        ssq += __shfl_down_sync(0xffffffffu, ssq, o);
        np += __shfl_down_sync(0xffffffffu, np, o);
        nv += __shfl_down_sync(0xffffffffu, nv, o);
        p0 = min(p0, __shfl_down_sync(0xffffffffu, p0, o));
        vlast = max(vlast, __shfl_down_sync(0xffffffffu, vlast, o));
        int oa = __shfl_down_sync(0xffffffffu, va, o);
        int ob = __shfl_down_sync(0xffffffffu, vb, o);
        int m1 = min(va, oa);
        vb = min(max(va, oa), min(vb, ob));
        va = m1;
    }
    if (lane == 0) {
        fp1[0][wrp] = mx; fp1[1][wrp] = mn; fp1[2][wrp] = sum; fp1[3][wrp] = ssq;
        ip1[0][wrp] = np; ip1[1][wrp] = nv; ip1[2][wrp] = p0; ip1[3][wrp] = vlast;
        ip1[4][wrp] = va; ip1[5][wrp] = vb;
    }
    __syncthreads();
    if (wrp < 4) {
        float ident = (wrp == 0) ? -FLT_MAX : (wrp == 1) ? FLT_MAX : 0.0f;
        float v = (lane < NWARP) ? fp1[wrp][lane] : ident;
#pragma unroll
        for (int o = 8; o; o >>= 1) {
            float ov = __shfl_down_sync(0xffffffffu, v, o);
            v = (wrp == 0) ? fmaxf(v, ov) : (wrp == 1) ? fminf(v, ov) : (v + ov);
        }
        if (lane == 0) fres[wrp] = v;
    } else if (wrp < 8) {
        int q = wrp - 4;  // 0:np 1:nv 2:p0(min) 3:vlast(max)
        int ident = (q < 2) ? 0 : (q == 2) ? INT_MAX : INT_MIN;
        int v = (lane < NWARP) ? ip1[q][lane] : ident;
#pragma unroll
        for (int o = 8; o; o >>= 1) {
            int ov = __shfl_down_sync(0xffffffffu, v, o);
            v = (q < 2) ? (v + ov) : (q == 2) ? min(v, ov) : max(v, ov);
        }
        if (lane == 0) ires[q] = v;
    } else if (wrp == 8) {
        int a = (lane < NWARP) ? ip1[4][lane] : INT_MAX;
        int b = (lane < NWARP) ? ip1[5][lane] : INT_MAX;
#pragma unroll
        for (int o = 8; o; o >>= 1) {
            int oa = __shfl_down_sync(0xffffffffu, a, o);
            int ob = __shfl_down_sync(0xffffffffu, b, o);
            int m1 = min(a, oa);
            b = min(max(a, oa), min(b, ob));
            a = m1;
        }
        if (lane == 0) { ires[4] = a; ires[5] = b; }
    }
    __syncthreads();
    mx = fres[0]; mn = fres[1]; sum = fres[2]; ssq = fres[3];
    np = ires[0]; nv = ires[1]; p0 = ires[2]; vlast = ires[3];
    va = ires[4]; vb = ires[5];

    const bool valid = (np >= 1) && (nv >= 2);
    const int P0 = valid ? p0 : 0;
    const int V0 = valid ? va : 0;
    const int V1 = valid ? vb : 0;
    const int VL = valid ? vlast : 0;

    const float sp0 = re[P0], sv0 = re[V0];
    const float PH = sp0 - sv0;
    const float hh = (PH + sv0) * 0.5f;
    __syncthreads();  // all threads done reading fres/ires before reuse

    // ---- phase 2: trapezoid areas + half-height width ----
    float pa = 0.0f, a2 = 0.0f, a1 = 0.0f;
    int li = INT_MAX, ri = -1;
    const float hs = 0.5f / SRATE;
#pragma unroll 4
    for (int i = tid; i < LSIG; i += NTH) {
        float v = re[i];
        if (i < LSIG - 1) {
            float seg = (v + re[i + 1]) * hs;  // re[8192] lands in bufB: safe, unused
            if (i >= V0 && i <= VL - 2) pa += seg;
            if (i >= P0 && i <= V1 - 2) a2 += seg;
            if (i >= V0 && i <= P0 - 2) a1 += seg;
        }
        if (v >= hh) {
            if (i >= V0 && i < P0) li = min(li, i);
            if (i > V0 && i <= P0) ri = max(ri, i);
        }
    }
    // batched reduction: 3 sums + min + max, 2 barriers
#pragma unroll
    for (int o = 16; o; o >>= 1) {
        pa += __shfl_down_sync(0xffffffffu, pa, o);
        a2 += __shfl_down_sync(0xffffffffu, a2, o);
        a1 += __shfl_down_sync(0xffffffffu, a1, o);
        li = min(li, __shfl_down_sync(0xffffffffu, li, o));
        ri = max(ri, __shfl_down_sync(0xffffffffu, ri, o));
    }
    if (lane == 0) {
        fp1[0][wrp] = pa; fp1[1][wrp] = a2; fp1[2][wrp] = a1;
        ip1[0][wrp] = li; ip1[1][wrp] = ri;
    }
    __syncthreads();
    if (wrp < 3) {
        float v = (lane < NWARP) ? fp1[wrp][lane] : 0.0f;
#pragma unroll
        for (int o = 8; o; o >>= 1) v += __shfl_down_sync(0xffffffffu, v, o);
        if (lane == 0) fres[wrp] = v;
    } else if (wrp == 3) {
        int v = (lane < NWARP) ? ip1[0][lane] : INT_MAX;
#pragma unroll
        for (int o = 8; o; o >>= 1) v = min(v, __shfl_down_sync(0xffffffffu, v, o));
        if (lane == 0) ires[0] = v;
    } else if (wrp == 4) {
        int v = (lane < NWARP) ? ip1[1][lane] : INT_MIN;
#pragma unroll
        for (int o = 8; o; o >>= 1) v = max(v, __shfl_down_sync(0xffffffffu, v, o));
        if (lane == 0) ires[1] = v;
    }
    __syncthreads();
    pa = fres[0]; a2 = fres[1]; a1 = fres[2];
    li = ires[0]; ri = ires[1];
    if (li == INT_MAX) li = V0;
    if (ri == -1) ri = P0;
    const float pwhh = (float)(ri - li) * (1.0f / SRATE);
    __syncthreads();

    // ---- 4096-point Stockham radix-4 FFT (natural-order output) ----
    // stage 0: reads NATURAL bufA, writes swizzled bufB
#pragma unroll
    for (int k = 0; k < 2; k++) {
        int i = tid + k * NTH;
        float2 a = bufA[i];
        float2 b = bufA[i + 1024];
        float2 c = bufA[i + 2048];
        float2 d = bufA[i + 3072];

        float2 w1 = Wq(tab, i << 1);
        float2 w2 = cmul(w1, w1);
        float2 w3 = cmul(w2, w1);

        float2 apc = make_float2(a.x + c.x, a.y + c.y);
        float2 amc = make_float2(a.x - c.x, a.y - c.y);
        float2 bpd = make_float2(b.x + d.x, b.y + d.y);
        float2 jbmd = make_float2(-(b.y - d.y), b.x - d.x);

        int wb = i << 2;
        bufB[swz(wb)] = make_float2(apc.x + bpd.x, apc.y + bpd.y);
        bufB[swz(wb + 1)] = cmul(w1, make_float2(amc.x - jbmd.x, amc.y - jbmd.y));
        bufB[swz(wb + 2)] = cmul(w2, make_float2(apc.x - bpd.x, apc.y - bpd.y));
        bufB[swz(wb + 3)] = cmul(w3, make_float2(amc.x + jbmd.x, amc.y + jbmd.y));
    }
    __syncthreads();

    // stages 1..5: swizzled read/write, ping-pong
    float2* cur = bufB;
    float2* nxt = bufA;
#pragma unroll
    for (int t = 1; t < 6; t++) {
        const int s = 1 << (2 * t);
        const int sh = 1 + 2 * t;
#pragma unroll
        for (int k = 0; k < 2; k++) {
            int i = tid + k * NTH;
            int ps = i & ~(s - 1);
            int p = i >> (2 * t);
            int ri2 = swz(i);
            float2 a = cur[ri2];
            float2 b = cur[ri2 + 1024];
            float2 c = cur[ri2 + 2048];
            float2 d = cur[ri2 + 3072];

            float2 w1 = Wq(tab, p << sh);
            float2 w2 = cmul(w1, w1);
            float2 w3 = cmul(w2, w1);

            float2 apc = make_float2(a.x + c.x, a.y + c.y);
            float2 amc = make_float2(a.x - c.x, a.y - c.y);
            float2 bpd = make_float2(b.x + d.x, b.y + d.y);
            float2 jbmd = make_float2(-(b.y - d.y), b.x - d.x);

            int wb = i + 3 * ps;
            nxt[swz(wb)] = make_float2(apc.x + bpd.x, apc.y + bpd.y);
            nxt[swz(wb + s)] =
                cmul(w1, make_float2(amc.x - jbmd.x, amc.y - jbmd.y));
            nxt[swz(wb + 2 * s)] =
                cmul(w2, make_float2(apc.x - bpd.x, apc.y - bpd.y));
            nxt[swz(wb + 3 * s)] =
                cmul(w3, make_float2(amc.x + jbmd.x, amc.y + jbmd.y));
        }
        __syncthreads();
        float2* tmp = cur; cur = nxt; nxt = tmp;
    }
    // stage0 + 5 stages -> result in bufA (== cur)

    // ---- real-FFT unpack + magnitude sum (Hermitian-halved) ----
    // Z = FFT(x_even + i*x_odd); E = (Z[k]+conj Z[N2-k])/2, O = (Z[k]-conj Z[N2-k])/(2i)
    // X[k] = E + W^k O (k<4096), X[4096] = E0 - O0; |X[8192-k]| = |X[k]|.
    float ms = 0.0f;
#pragma unroll
    for (int k0 = 0; k0 < N2 / NTH; k0++) {
        int k = tid + k0 * NTH;
        int kp = (N2 - k) & (N2 - 1);
        float2 Zk = cur[swz(k)];
        float2 Zp = cur[swz(kp)];
        float Er = 0.5f * (Zk.x + Zp.x);
        float Ei = 0.5f * (Zk.y - Zp.y);
        float Or = 0.5f * (Zk.y + Zp.y);
        float Oi = 0.5f * (Zp.x - Zk.x);
        float2 w;
        if (k < 2048) {
            w = Wq(tab, k);
        } else {
            float2 u = Wq(tab, k - 2048);
            w = make_float2(u.y, -u.x);  // -i * u
        }
        float2 wo = cmul(w, make_float2(Or, Oi));
        if (k == 0) {
            ms += fabsf(Er + Or) + fabsf(Er - Or);  // |X[0]| + |X[4096]|
        } else {
            float xr = Er + wo.x, xi = Ei + wo.y;
            ms += 2.0f * fast_sqrt(fmaf(xr, xr, xi * xi));
        }
    }
    // final sum reduction
#pragma unroll
    for (int o = 16; o; o >>= 1) ms += __shfl_down_sync(0xffffffffu, ms, o);
    if (lane == 0) fp1[0][wrp] = ms;
    __syncthreads();
    if (wrp == 0) {
        float v = (lane < NWARP) ? fp1[0][lane] : 0.0f;
#pragma unroll
        for (int o = 8; o; o >>= 1) v += __shfl_down_sync(0xffffffffu, v, o);
        if (lane == 0) {
            float fftm = v * (1.0f / (float)LSIG);
            float mean = sum * (1.0f / (float)LSIG);
            float var = (ssq - sum * mean) * (1.0f / (float)(LSIG - 1));
            float* o_ = out + (size_t)blockIdx.x * 10;
            o_[0] = mx;
            o_[1] = mx - mn;
            o_[2] = var;
            o_[3] = sqrtf(var);
            o_[4] = fftm;
            o_[5] = valid ? pa : 0.0f;
            o_[6] = valid ? a2 : 0.0f;
            o_[7] = valid ? PH : 0.0f;
            o_[8] = valid ? a1 : 0.0f;
            o_[9] = valid ? pwhh : 0.0f;
        }
    }
}

extern "C" void kernel_launch(void* const* d_in, const int* in_sizes, int n_in,
                              void* d_out, int out_size) {
    const float* x = (const float*)d_in[0];
    float* out = (float*)d_out;
    int nrow = in_sizes[0] / LSIG;

    (void)n_in; (void)out_size;

    const int smem = (2 * N2 + 1025) * (int)sizeof(float2);  // 73736
    cudaFuncSetAttribute(feat_kernel, cudaFuncAttributeMaxDynamicSharedMemorySize, smem);

    tab_init_kernel<<<5, 256>>>();
    feat_kernel<<<nrow, NTH, smem>>>(x, out);
}

// round 13
// speedup vs baseline: 2.1200x; 1.1739x over previous
#include <cuda_runtime.h>
#include <math.h>
#include <float.h>
#include <limits.h>

#define LSIG 8192
#define N2   4096
#define NTH  512
#define NWARP 16
#define SRATE 30.0f

// quarter-wave table: (cos, sin)(2*pi*k/8192) for k = 0..1024
__device__ float2 g_tab[1025];

__global__ void tab_init_kernel() {
    int k = blockIdx.x * blockDim.x + threadIdx.x;
    if (k <= 1024) {
        double a = 2.0 * 3.14159265358979323846 * (double)k / 8192.0;
        g_tab[k] = make_float2((float)cos(a), (float)sin(a));
    }
}

// sqrt on the FMA pipe (avoid MUFU bottleneck). Safe at x == 0.
__device__ __forceinline__ float fast_sqrt(float x) {
    float xh = 0.5f * x;
    int i = __float_as_int(x);
    i = 0x5f375a86 - (i >> 1);
    float y = __int_as_float(i);
    y = y * (1.5f - xh * y * y);
    y = y * (1.5f - xh * y * y);
    return x * y;
}

// XOR bank swizzle on complex index (FFT stages only).
__device__ __forceinline__ int swz(int a) { return a ^ ((a >> 4) & 15); }

// e^{-2*pi*i*q/8192} for q in [0, 2048), via quarter-wave table
__device__ __forceinline__ float2 Wq(const float2* __restrict__ tab, int q) {
    if (q <= 1024) {
        float2 t = tab[q];
        return make_float2(t.x, -t.y);
    }
    float2 t = tab[2048 - q];
    return make_float2(t.y, -t.x);
}

__device__ __forceinline__ float2 cmul(float2 a, float2 b) {
    return make_float2(fmaf(a.x, b.x, -(a.y * b.y)), fmaf(a.x, b.y, a.y * b.x));
}
__device__ __forceinline__ float2 cadd(float2 a, float2 b) {
    return make_float2(a.x + b.x, a.y + b.y);
}
__device__ __forceinline__ float2 csub(float2 a, float2 b) {
    return make_float2(a.x - b.x, a.y - b.y);
}
// i * a
__device__ __forceinline__ float2 jmul(float2 a) { return make_float2(-a.y, a.x); }

// One radix-8 Stockham stage. S = 8^t. NATREAD: read natural layout (stage 0).
// TW: apply twiddles (false for last stage where p == 0).
template <int S, bool TW, bool NATREAD>
__device__ __forceinline__ void r8_stage(const float2* __restrict__ cur,
                                         float2* __restrict__ nxt,
                                         const float2* __restrict__ tab,
                                         int i) {
    const int base = NATREAD ? i : swz(i);
    float2 a0 = cur[base];
    float2 a1 = cur[base + 512];
    float2 a2 = cur[base + 1024];
    float2 a3 = cur[base + 1536];
    float2 a4 = cur[base + 2048];
    float2 a5 = cur[base + 2560];
    float2 a6 = cur[base + 3072];
    float2 a7 = cur[base + 3584];

    // E = radix-4 of (a0,a2,a4,a6)
    float2 ta = cadd(a0, a4), tb = csub(a0, a4);
    float2 tc = cadd(a2, a6), td = jmul(csub(a2, a6));
    float2 E0 = cadd(ta, tc);
    float2 E1 = csub(tb, td);
    float2 E2 = csub(ta, tc);
    float2 E3 = cadd(tb, td);
    // O = radix-4 of (a1,a3,a5,a7)
    ta = cadd(a1, a5); tb = csub(a1, a5);
    tc = cadd(a3, a7); td = jmul(csub(a3, a7));
    float2 O0 = cadd(ta, tc);
    float2 O1 = csub(tb, td);
    float2 O2 = csub(ta, tc);
    float2 O3 = cadd(tb, td);

    // rotate odd outputs by w8^r
    const float C = 0.70710678118654752f;
    float2 R1 = make_float2(C * (O1.x + O1.y), C * (O1.y - O1.x));
    float2 R2 = make_float2(O2.y, -O2.x);
    float2 R3 = make_float2(C * (O3.y - O3.x), -C * (O3.x + O3.y));

    if (TW) {
        const int ps = i & ~(S - 1);
        const int wb = i + 7 * ps;
        // q8 = 2*ps <= 1022 -> always in quarter-table direct range (branch-free)
        float2 t1 = tab[ps << 1];
        float2 w1 = make_float2(t1.x, -t1.y);
        float2 w2 = cmul(w1, w1);
        float2 w4 = cmul(w2, w2);

        nxt[swz(wb)] = cadd(E0, O0);
        nxt[swz(wb + 4 * S)] = cmul(w4, csub(E0, O0));
        float2 wr = w1;
        nxt[swz(wb + S)] = cmul(wr, cadd(E1, R1));
        nxt[swz(wb + 5 * S)] = cmul(cmul(wr, w4), csub(E1, R1));
        wr = w2;
        nxt[swz(wb + 2 * S)] = cmul(wr, cadd(E2, R2));
        nxt[swz(wb + 6 * S)] = cmul(cmul(wr, w4), csub(E2, R2));
        wr = cmul(w2, w1);
        nxt[swz(wb + 3 * S)] = cmul(wr, cadd(E3, R3));
        nxt[swz(wb + 7 * S)] = cmul(cmul(wr, w4), csub(E3, R3));
    } else {
        // S == 512: ps = 0, all twiddles = 1; swz(i + 512r) = swz(i) + 512r
        const int sb = swz(i);
        nxt[sb] = cadd(E0, O0);
        nxt[sb + 512] = cadd(E1, R1);
        nxt[sb + 1024] = cadd(E2, R2);
        nxt[sb + 1536] = cadd(E3, R3);
        nxt[sb + 2048] = csub(E0, O0);
        nxt[sb + 2560] = csub(E1, R1);
        nxt[sb + 3072] = csub(E2, R2);
        nxt[sb + 3584] = csub(E3, R3);
    }
}

// dynamic smem: bufA[4096] | bufB[4096] | tab[1025]  (float2) = 73736 bytes
extern __shared__ float2 s_dyn2[];

__global__ __launch_bounds__(NTH, 3)
void feat_kernel(const float* __restrict__ x, float* __restrict__ out) {
    float2* bufA = s_dyn2;
    float2* bufB = s_dyn2 + N2;
    float2* tab = s_dyn2 + 2 * N2;

    __shared__ float fp1[4][NWARP];
    __shared__ int ip1[6][NWARP];
    __shared__ float fres[4];
    __shared__ int ires[6];

    const int tid = threadIdx.x;
    const int lane = tid & 31;
    const int wrp = tid >> 5;
    const float2* __restrict__ sig2 =
        (const float2*)(x + (size_t)blockIdx.x * LSIG);

    // stage twiddle table
#pragma unroll
    for (int i = tid; i < 1025; i += NTH) tab[i] = g_tab[i];

    // ---- pass A: load (natural layout == even/odd packed complex) + stats ----
    float mx = -FLT_MAX, mn = FLT_MAX, sum = 0.0f, ssq = 0.0f;
#pragma unroll
    for (int k = 0; k < N2 / NTH; k++) {
        int n = tid + k * NTH;
        float2 v = sig2[n];
        mx = fmaxf(mx, fmaxf(v.x, v.y));
        mn = fminf(mn, fminf(v.x, v.y));
        sum += v.x + v.y;
        ssq = fmaf(v.x, v.x, ssq);
        ssq = fmaf(v.y, v.y, ssq);
        bufA[n] = v;
    }
    __syncthreads();

    const float* __restrict__ re = (const float*)bufA;

    // ---- phase 1: peak/valley structure (float2 + shfl neighbors) ----
    int np = 0, nv = 0, p0 = INT_MAX, va = INT_MAX, vb = INT_MAX, vlast = -1;
#pragma unroll
    for (int k = 0; k < N2 / NTH; k++) {
        int n = tid + k * NTH;
        float2 v = bufA[n];
        float pl = __shfl_up_sync(0xffffffffu, v.y, 1);
        float nr = __shfl_down_sync(0xffffffffu, v.x, 1);
        if (lane == 0) pl = re[max(2 * n - 1, 0)];
        if (lane == 31) nr = re[2 * n + 2];  // n=4095 reads bufB[0]: unused (inb false)
        int ie = 2 * n, io = ie + 1;
        bool inb_e = (n > 0);
        if (inb_e && v.x > pl && v.x > v.y) { np++; p0 = min(p0, ie); }
        if (inb_e && v.x < pl && v.x < v.y) {
            nv++; vlast = ie;
            if (va == INT_MAX) va = ie; else if (vb == INT_MAX) vb = ie;
        }
        bool inb_o = (n < N2 - 1);
        if (inb_o && v.y > v.x && v.y > nr) { np++; p0 = min(p0, io); }
        if (inb_o && v.y < v.x && v.y < nr) {
            nv++; vlast = io;
            if (va == INT_MAX) va = io; else if (vb == INT_MAX) vb = io;
        }
    }

    // ---- batched block reduction: all phase-1 quantities, 2 barriers ----
#pragma unroll
    for (int o = 16; o; o >>= 1) {
        mx = fmaxf(mx, __shfl_down_sync(0xffffffffu, mx, o));
        mn = fminf(mn, __shfl_down_sync(0xffffffffu, mn, o));
        sum += __shfl_down_sync(0xffffffffu, sum, o);
        ssq += __shfl_down_sync(0xffffffffu, ssq, o);
        np += __shfl_down_sync(0xffffffffu, np, o);
        nv += __shfl_down_sync(0xffffffffu, nv, o);
        p0 = min(p0, __shfl_down_sync(0xffffffffu, p0, o));
        vlast = max(vlast, __shfl_down_sync(0xffffffffu, vlast, o));
        int oa = __shfl_down_sync(0xffffffffu, va, o);
        int ob = __shfl_down_sync(0xffffffffu, vb, o);
        int m1 = min(va, oa);
        vb = min(max(va, oa), min(vb, ob));
        va = m1;
    }
    if (lane == 0) {
        fp1[0][wrp] = mx; fp1[1][wrp] = mn; fp1[2][wrp] = sum; fp1[3][wrp] = ssq;
        ip1[0][wrp] = np; ip1[1][wrp] = nv; ip1[2][wrp] = p0; ip1[3][wrp] = vlast;
        ip1[4][wrp] = va; ip1[5][wrp] = vb;
    }
    __syncthreads();
    if (wrp < 4) {
        float ident = (wrp == 0) ? -FLT_MAX : (wrp == 1) ? FLT_MAX : 0.0f;
        float v = (lane < NWARP) ? fp1[wrp][lane] : ident;
#pragma unroll
        for (int o = 8; o; o >>= 1) {
            float ov = __shfl_down_sync(0xffffffffu, v, o);
            v = (wrp == 0) ? fmaxf(v, ov) : (wrp == 1) ? fminf(v, ov) : (v + ov);
        }
        if (lane == 0) fres[wrp] = v;
    } else if (wrp < 8) {
        int q = wrp - 4;  // 0:np 1:nv 2:p0(min) 3:vlast(max)
        int ident = (q < 2) ? 0 : (q == 2) ? INT_MAX : INT_MIN;
        int v = (lane < NWARP) ? ip1[q][lane] : ident;
#pragma unroll
        for (int o = 8; o; o >>= 1) {
            int ov = __shfl_down_sync(0xffffffffu, v, o);
            v = (q < 2) ? (v + ov) : (q == 2) ? min(v, ov) : max(v, ov);
        }
        if (lane == 0) ires[q] = v;
    } else if (wrp == 8) {
        int a = (lane < NWARP) ? ip1[4][lane] : INT_MAX;
        int b = (lane < NWARP) ? ip1[5][lane] : INT_MAX;
#pragma unroll
        for (int o = 8; o; o >>= 1) {
            int oa = __shfl_down_sync(0xffffffffu, a, o);
            int ob = __shfl_down_sync(0xffffffffu, b, o);
            int m1 = min(a, oa);
            b = min(max(a, oa), min(b, ob));
            a = m1;
        }
        if (lane == 0) { ires[4] = a; ires[5] = b; }
    }
    __syncthreads();
    mx = fres[0]; mn = fres[1]; sum = fres[2]; ssq = fres[3];
    np = ires[0]; nv = ires[1]; p0 = ires[2]; vlast = ires[3];
    va = ires[4]; vb = ires[5];

    const bool valid = (np >= 1) && (nv >= 2);
    const int P0 = valid ? p0 : 0;
    const int V0 = valid ? va : 0;
    const int V1 = valid ? vb : 0;
    const int VL = valid ? vlast : 0;

    const float sp0 = re[P0], sv0 = re[V0];
    const float PH = sp0 - sv0;
    const float hh = (PH + sv0) * 0.5f;
    __syncthreads();  // all threads done reading fres/ires before reuse

    // ---- phase 2: trapezoid areas + half-height width (float2 + shfl) ----
    float pa = 0.0f, a2s = 0.0f, a1s = 0.0f;
    int li = INT_MAX, ri = -1;
    const float hs = 0.5f / SRATE;
#pragma unroll
    for (int k = 0; k < N2 / NTH; k++) {
        int n = tid + k * NTH;
        float2 v = bufA[n];
        float nr = __shfl_down_sync(0xffffffffu, v.x, 1);
        if (lane == 31) nr = re[2 * n + 2];  // n=4095: garbage, predicated off
        int ie = 2 * n, io = ie + 1;
        float se = (v.x + v.y) * hs;
        float so = (v.y + nr) * hs;
        if (ie >= V0 && ie <= VL - 2) pa += se;
        if (ie >= P0 && ie <= V1 - 2) a2s += se;
        if (ie >= V0 && ie <= P0 - 2) a1s += se;
        if (v.x >= hh) {
            if (ie >= V0 && ie < P0) li = min(li, ie);
            if (ie > V0 && ie <= P0) ri = max(ri, ie);
        }
        if (io >= V0 && io <= VL - 2) pa += so;
        if (io >= P0 && io <= V1 - 2) a2s += so;
        if (io >= V0 && io <= P0 - 2) a1s += so;
        if (v.y >= hh) {
            if (io >= V0 && io < P0) li = min(li, io);
            if (io > V0 && io <= P0) ri = max(ri, io);
        }
    }
#pragma unroll
    for (int o = 16; o; o >>= 1) {
        pa += __shfl_down_sync(0xffffffffu, pa, o);
        a2s += __shfl_down_sync(0xffffffffu, a2s, o);
        a1s += __shfl_down_sync(0xffffffffu, a1s, o);
        li = min(li, __shfl_down_sync(0xffffffffu, li, o));
        ri = max(ri, __shfl_down_sync(0xffffffffu, ri, o));
    }
    if (lane == 0) {
        fp1[0][wrp] = pa; fp1[1][wrp] = a2s; fp1[2][wrp] = a1s;
        ip1[0][wrp] = li; ip1[1][wrp] = ri;
    }
    __syncthreads();
    if (wrp < 3) {
        float v = (lane < NWARP) ? fp1[wrp][lane] : 0.0f;
#pragma unroll
        for (int o = 8; o; o >>= 1) v += __shfl_down_sync(0xffffffffu, v, o);
        if (lane == 0) fres[wrp] = v;
    } else if (wrp == 3) {
        int v = (lane < NWARP) ? ip1[0][lane] : INT_MAX;
#pragma unroll
        for (int o = 8; o; o >>= 1) v = min(v, __shfl_down_sync(0xffffffffu, v, o));
        if (lane == 0) ires[0] = v;
    } else if (wrp == 4) {
        int v = (lane < NWARP) ? ip1[1][lane] : INT_MIN;
#pragma unroll
        for (int o = 8; o; o >>= 1) v = max(v, __shfl_down_sync(0xffffffffu, v, o));
        if (lane == 0) ires[1] = v;
    }
    __syncthreads();
    pa = fres[0]; a2s = fres[1]; a1s = fres[2];
    li = ires[0]; ri = ires[1];
    if (li == INT_MAX) li = V0;
    if (ri == -1) ri = P0;
    const float pwhh = (float)(ri - li) * (1.0f / SRATE);
    __syncthreads();

    // ---- 4096-point Stockham radix-8 FFT, 4 stages, natural-order output ----
    r8_stage<1, true, true>(bufA, bufB, tab, tid);    // t=0: natural read
    __syncthreads();
    r8_stage<8, true, false>(bufB, bufA, tab, tid);   // t=1
    __syncthreads();
    r8_stage<64, true, false>(bufA, bufB, tab, tid);  // t=2
    __syncthreads();
    r8_stage<512, false, false>(bufB, bufA, tab, tid);  // t=3: twiddle-free
    __syncthreads();
    const float2* __restrict__ cur = bufA;

    // ---- real-FFT unpack + magnitude sum (Hermitian-halved) ----
    float ms = 0.0f;
#pragma unroll
    for (int k0 = 0; k0 < N2 / NTH; k0++) {
        int k = tid + k0 * NTH;
        int kp = (N2 - k) & (N2 - 1);
        float2 Zk = cur[swz(k)];
        float2 Zp = cur[swz(kp)];
        float Er = 0.5f * (Zk.x + Zp.x);
        float Ei = 0.5f * (Zk.y - Zp.y);
        float Or = 0.5f * (Zk.y + Zp.y);
        float Oi = 0.5f * (Zp.x - Zk.x);
        float2 w;
        if (k0 < 2) {            // k <= 1023: quarter table direct
            float2 t = tab[k];
            w = make_float2(t.x, -t.y);
        } else if (k0 < 4) {     // k in [1024, 2048)
            w = Wq(tab, k);
        } else {                 // k in [2048, 4096): w = -i * Wq(k-2048)
            float2 u = Wq(tab, k - 2048);
            w = make_float2(u.y, -u.x);
        }
        float2 wo = cmul(w, make_float2(Or, Oi));
        if (k == 0) {
            ms += fabsf(Er + Or) + fabsf(Er - Or);  // |X[0]| + |X[4096]|
        } else {
            float xr = Er + wo.x, xi = Ei + wo.y;
            ms += 2.0f * fast_sqrt(fmaf(xr, xr, xi * xi));
        }
    }
#pragma unroll
    for (int o = 16; o; o >>= 1) ms += __shfl_down_sync(0xffffffffu, ms, o);
    if (lane == 0) fp1[0][wrp] = ms;
    __syncthreads();
    if (wrp == 0) {
        float v = (lane < NWARP) ? fp1[0][lane] : 0.0f;
#pragma unroll
        for (int o = 8; o; o >>= 1) v += __shfl_down_sync(0xffffffffu, v, o);
        if (lane == 0) {
            float fftm = v * (1.0f / (float)LSIG);
            float mean = sum * (1.0f / (float)LSIG);
            float var = (ssq - sum * mean) * (1.0f / (float)(LSIG - 1));
            float* o_ = out + (size_t)blockIdx.x * 10;
            o_[0] = mx;
            o_[1] = mx - mn;
            o_[2] = var;
            o_[3] = sqrtf(var);
            o_[4] = fftm;
            o_[5] = valid ? pa : 0.0f;
            o_[6] = valid ? a2s : 0.0f;
            o_[7] = valid ? PH : 0.0f;
            o_[8] = valid ? a1s : 0.0f;
            o_[9] = valid ? pwhh : 0.0f;
        }
    }
}

extern "C" void kernel_launch(void* const* d_in, const int* in_sizes, int n_in,
                              void* d_out, int out_size) {
    const float* x = (const float*)d_in[0];
    float* out = (float*)d_out;
    int nrow = in_sizes[0] / LSIG;

    (void)n_in; (void)out_size;

    const int smem = (2 * N2 + 1025) * (int)sizeof(float2);  // 73736
    cudaFuncSetAttribute(feat_kernel, cudaFuncAttributeMaxDynamicSharedMemorySize, smem);

    tab_init_kernel<<<5, 256>>>();
    feat_kernel<<<nrow, NTH, smem>>>(x, out);
}